// round 17
// baseline (speedup 1.0000x reference)
#include <cuda_runtime.h>
#include <cuda_fp16.h>
#include <math.h>
#include <stdint.h>

// Problem constants
#define T_TOK   16384
#define HDIM    1024
#define MDIM    2048
#define NEXP    16
#define NASSIGN (T_TOK * 2)     // 32768
#define MAX_TILES 272           // sum ceil(ne/128) <= 256 + 16
#define BK 64
#define BN 256

// ---------------- scratch (device globals; no allocation allowed) ----------
static __device__ __half g_Xg[(size_t)NASSIGN * HDIM];        // 64 MB gathered X f16
static __device__ __half g_W1t[(size_t)NEXP * MDIM * HDIM];   // 64 MB [e][n][k] f16
static __device__ __half g_W2t[(size_t)NEXP * HDIM * MDIM];   // 64 MB [e][n][k] f16
static __device__ __half g_H[(size_t)NASSIGN * MDIM];         // 128 MB f16
static __device__ float  g_Y[(size_t)NASSIGN * HDIM];         // 128 MB
static __device__ int    g_counts[NEXP];
static __device__ int    g_offsets[NEXP];
static __device__ int    g_cursor[NEXP];
static __device__ int    g_token_ids[NASSIGN];
static __device__ int    g_pos_for[NASSIGN];
static __device__ int    g_top_idx[NASSIGN];
static __device__ float  g_top_w[NASSIGN];
static __device__ int    g_tile_e[MAX_TILES];
static __device__ int    g_tile_row[MAX_TILES];
static __device__ int    g_tile_nr[MAX_TILES];
static __device__ int    g_ntiles;

// ---------------- PTX helpers (base sm_103 features only) -------------------
__device__ __forceinline__ uint32_t smem_u32(const void* p) {
    uint32_t a;
    asm("{ .reg .u64 t; cvta.to.shared.u64 t, %1; cvt.u32.u64 %0, t; }" : "=r"(a) : "l"(p));
    return a;
}

__device__ __forceinline__ void cp16(uint32_t saddr, const void* gaddr) {
    asm volatile("cp.async.cg.shared.global [%0], [%1], 16;" :: "r"(saddr), "l"(gaddr));
}
#define CP_COMMIT() asm volatile("cp.async.commit_group;")
#define CP_WAIT(n)  asm volatile("cp.async.wait_group %0;" :: "n"(n))

#define LDSM_X4(d0, d1, d2, d3, addr)                                       \
    asm volatile("ldmatrix.sync.aligned.m8n8.x4.shared.b16 {%0,%1,%2,%3}, [%4];" \
        : "=r"(d0), "=r"(d1), "=r"(d2), "=r"(d3) : "r"(addr))

__device__ __forceinline__ void mma16816(float* c, const uint32_t* a, const uint32_t* b) {
    asm volatile(
        "mma.sync.aligned.m16n8k16.row.col.f32.f16.f16.f32 "
        "{%0,%1,%2,%3}, {%4,%5,%6,%7}, {%8,%9}, {%0,%1,%2,%3};"
        : "+f"(c[0]), "+f"(c[1]), "+f"(c[2]), "+f"(c[3])
        : "r"(a[0]), "r"(a[1]), "r"(a[2]), "r"(a[3]), "r"(b[0]), "r"(b[1]));
}

// ---------------- small kernels ---------------------------------------------
__global__ void zero_counts_kernel() {
    int i = threadIdx.x;
    if (i < NEXP) g_counts[i] = 0;
}

__global__ void gate_kernel(const float* __restrict__ X,
                            const float* __restrict__ Wg,
                            const float* __restrict__ bg) {
    const int t   = blockIdx.x;
    const int tid = threadIdx.x;
    __shared__ float sm[NEXP][128];
    float acc[NEXP];
#pragma unroll
    for (int e = 0; e < NEXP; e++) acc[e] = 0.f;
    const float* x = X + (size_t)t * HDIM;
    for (int h = tid; h < HDIM; h += 128) {
        float xv = x[h];
        const float4* w4 = reinterpret_cast<const float4*>(Wg + (size_t)h * NEXP);
#pragma unroll
        for (int q = 0; q < 4; q++) {
            float4 w = w4[q];
            acc[q * 4 + 0] += xv * w.x;
            acc[q * 4 + 1] += xv * w.y;
            acc[q * 4 + 2] += xv * w.z;
            acc[q * 4 + 3] += xv * w.w;
        }
    }
#pragma unroll
    for (int e = 0; e < NEXP; e++) sm[e][tid] = acc[e];
    __syncthreads();
    for (int s = 64; s > 0; s >>= 1) {
        if (tid < s) {
#pragma unroll
            for (int e = 0; e < NEXP; e++) sm[e][tid] += sm[e][tid + s];
        }
        __syncthreads();
    }
    if (tid == 0) {
        float l[NEXP];
#pragma unroll
        for (int e = 0; e < NEXP; e++) l[e] = sm[e][0] + bg[e];
        int i0 = 0;
#pragma unroll
        for (int e = 1; e < NEXP; e++) if (l[e] > l[i0]) i0 = e;
        int i1 = (i0 == 0) ? 1 : 0;
#pragma unroll
        for (int e = 0; e < NEXP; e++) if (e != i0 && l[e] > l[i1]) i1 = e;
        float e1 = __expf(l[i1] - l[i0]);
        float s  = 1.f + e1;
        g_top_idx[2 * t + 0] = i0;  g_top_w[2 * t + 0] = 1.f / s;
        g_top_idx[2 * t + 1] = i1;  g_top_w[2 * t + 1] = e1 / s;
        atomicAdd(&g_counts[i0], 1);
        atomicAdd(&g_counts[i1], 1);
    }
}

__global__ void scan_kernel() {
    if (threadIdx.x == 0) {
        int off = 0;
        for (int e = 0; e < NEXP; e++) {
            g_offsets[e] = off;
            g_cursor[e]  = off;
            off += g_counts[e];
        }
        int nt = 0;
        for (int e = 0; e < NEXP; e++) {
            int ne = g_counts[e];
            for (int r = 0; r < ne; r += 128) {
                g_tile_e[nt]   = e;
                g_tile_row[nt] = g_offsets[e] + r;
                g_tile_nr[nt]  = (ne - r < 128) ? (ne - r) : 128;
                nt++;
            }
        }
        g_ntiles = nt;
    }
}

__global__ void scatter_kernel() {
    int idx = blockIdx.x * blockDim.x + threadIdx.x;
    if (idx >= NASSIGN) return;
    int t = idx >> 1;
    int e = g_top_idx[idx];
    int pos = atomicAdd(&g_cursor[e], 1);
    g_token_ids[pos] = t;
    g_pos_for[idx]   = pos;
}

// ---------------- conversion kernels ---------------------------------------
__global__ void gather_convert_x(const float* __restrict__ X) {
    const int p = blockIdx.x;
    const int t = g_token_ids[p];
    const float4* src = reinterpret_cast<const float4*>(X + (size_t)t * HDIM);
    __half2* dh = reinterpret_cast<__half2*>(g_Xg + (size_t)p * HDIM);
    for (int c = threadIdx.x; c < HDIM / 4; c += blockDim.x) {
        float4 v = src[c];
        dh[c * 2]     = __halves2half2(__float2half_rn(v.x), __float2half_rn(v.y));
        dh[c * 2 + 1] = __halves2half2(__float2half_rn(v.z), __float2half_rn(v.w));
    }
}

// W: [e][KD][ND] fp32 -> [e][ND][KD] f16 (K-major)
template <int KD, int ND>
__global__ __launch_bounds__(256) void trans_convert(const float* __restrict__ W,
                                                     __half* __restrict__ out) {
    __shared__ float s[32][33];
    const int e  = blockIdx.z;
    const int k0 = blockIdx.y * 32;
    const int n0 = blockIdx.x * 32;
    const int tx = threadIdx.x & 31;
    const int ty = threadIdx.x >> 5;   // 0..7
    const float* Wp = W + (size_t)e * KD * ND;
#pragma unroll
    for (int i = 0; i < 4; i++) {
        int kr = ty + i * 8;
        s[kr][tx] = Wp[(size_t)(k0 + kr) * ND + n0 + tx];
    }
    __syncthreads();
    __half* oh = out + (size_t)e * ND * KD;
#pragma unroll
    for (int i = 0; i < 4; i++) {
        int nr = ty + i * 8;
        oh[(size_t)(n0 + nr) * KD + k0 + tx] = __float2half_rn(s[tx][nr]);
    }
}

// ---------------- warp-MMA grouped GEMM (single f16) ------------------------
// BM=128, BN=256, BK=64. 256 threads = 8 warps, warp grid 2(m) x 4(n),
// warp tile 64x64 -> per k16: 8 LDSM.x4 vs 32 HMMA (ratio 4.0).
// SMEM: A [2][128][72], B [2][256][72] halves = 36864 + 73728 = 110592 B.
// Row stride 144 B -> 8 consecutive rows hit distinct 16B banks (conflict-free).
#define ROWH  72
#define ASTG  18432
#define BSTG  36864
#define SMEM_BYTES 110592

template <int KTOT, int NOUT, bool IS_G1>
__global__ __launch_bounds__(256) void gemm_mma(const float* __restrict__ bias) {
    const int ti = blockIdx.y;
    if (ti >= g_ntiles) return;
    extern __shared__ char smem[];
    const uint32_t sb    = smem_u32(smem);
    const uint32_t ABase = sb;
    const uint32_t BBase = sb + 2 * ASTG;

    const int tid  = threadIdx.x;
    const int lane = tid & 31;
    const int wid  = tid >> 5;
    const int wm   = wid >> 2;       // 0..1  (m offset wm*64)
    const int wn   = wid & 3;        // 0..3  (n offset wn*64)

    const int e     = g_tile_e[ti];
    const int row0  = g_tile_row[ti];
    const int nrows = g_tile_nr[ti];
    const int n0    = blockIdx.x * BN;
    const int bRow0 = e * NOUT + n0;

    const __half* __restrict__ A0 = IS_G1 ? g_Xg  : g_H;
    const __half* __restrict__ B0 = IS_G1 ? g_W1t : g_W2t;

    float acc[4][8][4];
#pragma unroll
    for (int i = 0; i < 4; i++)
#pragma unroll
        for (int j = 0; j < 8; j++)
#pragma unroll
            for (int q = 0; q < 4; q++) acc[i][j][q] = 0.f;

    auto load_stage = [&](int s, int b) {
        const int k0 = s * BK;
        const uint32_t ah = ABase + b * ASTG;
        const uint32_t bh = BBase + b * BSTG;
        // A: 128 rows x 8 chunks = 1024 chunks (4/thread)
#pragma unroll
        for (int i = 0; i < 4; i++) {
            int m = tid + i * 256;
            int r = m >> 3, c = m & 7;
            int ar = row0 + r;
            if (ar >= NASSIGN) ar = NASSIGN - 1;
            size_t ago = (size_t)ar * KTOT + k0 + c * 8;
            cp16(ah + (uint32_t)(r * (ROWH * 2) + c * 16), A0 + ago);
        }
        // B: 256 rows x 8 chunks = 2048 chunks (8/thread)
#pragma unroll
        for (int i = 0; i < 8; i++) {
            int m = tid + i * 256;
            int r = m >> 3, c = m & 7;
            size_t bgo = (size_t)(bRow0 + r) * KTOT + k0 + c * 8;
            cp16(bh + (uint32_t)(r * (ROWH * 2) + c * 16), B0 + bgo);
        }
        CP_COMMIT();
    };

    constexpr int NST = KTOT / BK;
    load_stage(0, 0);
    load_stage(1, 1);

    for (int s = 0; s < NST; s++) {
        const int b = s & 1;
        if (s == NST - 1) { CP_WAIT(0); } else { CP_WAIT(1); }
        __syncthreads();

        const uint32_t ah = ABase + b * ASTG;
        const uint32_t bh = BBase + b * BSTG;

#pragma unroll
        for (int kk = 0; kk < BK; kk += 16) {
            uint32_t af[4][4], bf[4][4];
            // A fragments: four m16 tiles (m64 x k16)
            const uint32_t arow = (uint32_t)(wm * 64 + (lane & 15));
            const uint32_t akof = (uint32_t)((kk + ((lane >> 4) << 3)) * 2);
#pragma unroll
            for (int mt = 0; mt < 4; mt++) {
                uint32_t ad = ah + (arow + mt * 16) * (ROWH * 2) + akof;
                LDSM_X4(af[mt][0], af[mt][1], af[mt][2], af[mt][3], ad);
            }
            // B fragments: four n16 tiles (n64 x k16) -> 8 n8 frags
            const int g = lane >> 3;
            const uint32_t brow = (uint32_t)(wn * 64 + ((g >> 1) << 3) + (lane & 7));
            const uint32_t bkof = (uint32_t)((kk + ((g & 1) << 3)) * 2);
#pragma unroll
            for (int nt = 0; nt < 4; nt++) {
                uint32_t bd = bh + (brow + nt * 16) * (ROWH * 2) + bkof;
                LDSM_X4(bf[nt][0], bf[nt][1], bf[nt][2], bf[nt][3], bd);
            }
#pragma unroll
            for (int mt = 0; mt < 4; mt++) {
#pragma unroll
                for (int nb = 0; nb < 8; nb++) {
                    mma16816(acc[mt][nb], af[mt], &bf[nb >> 1][(nb & 1) * 2]);
                }
            }
        }
        __syncthreads();
        if (s + 2 < NST) load_stage(s + 2, b);
    }

    // epilogue. acc[mt][nb] = {c0,c1,c2,c3}: rows (lane>>2)+{0,8}, cols (lane&3)*2+{0,1}
    const float* bp = bias + (size_t)e * NOUT + n0;
#pragma unroll
    for (int mt = 0; mt < 4; mt++) {
#pragma unroll
        for (int half = 0; half < 2; half++) {
            const int r = wm * 64 + mt * 16 + (lane >> 2) + half * 8;
            if (r >= nrows) continue;
            const size_t orow = (size_t)(row0 + r);
#pragma unroll
            for (int nb = 0; nb < 8; nb++) {
                const int col = wn * 64 + nb * 8 + (lane & 3) * 2;
                float v0 = acc[mt][nb][half * 2 + 0] + bp[col];
                float v1 = acc[mt][nb][half * 2 + 1] + bp[col + 1];
                if (IS_G1) {
                    v0 = fmaxf(v0, 0.f);
                    v1 = fmaxf(v1, 0.f);
                    *reinterpret_cast<__half2*>(g_H + orow * NOUT + n0 + col) =
                        __halves2half2(__float2half_rn(v0), __float2half_rn(v1));
                } else {
                    float2 v; v.x = v0; v.y = v1;
                    *reinterpret_cast<float2*>(g_Y + orow * NOUT + n0 + col) = v;
                }
            }
        }
    }
}

// ---------------- combine ---------------------------------------------------
__global__ void combine_kernel(float* __restrict__ out) {
    const int t  = blockIdx.x;
    const int p0 = g_pos_for[2 * t + 0];
    const int p1 = g_pos_for[2 * t + 1];
    const float w0 = g_top_w[2 * t + 0];
    const float w1 = g_top_w[2 * t + 1];
    const float4* y0 = reinterpret_cast<const float4*>(g_Y + (size_t)p0 * HDIM);
    const float4* y1 = reinterpret_cast<const float4*>(g_Y + (size_t)p1 * HDIM);
    float4* o = reinterpret_cast<float4*>(out + (size_t)t * HDIM);
    int n = threadIdx.x;
    float4 a = y0[n];
    float4 b = y1[n];
    float4 v;
    v.x = w0 * a.x + w1 * b.x;
    v.y = w0 * a.y + w1 * b.y;
    v.z = w0 * a.z + w1 * b.z;
    v.w = w0 * a.w + w1 * b.w;
    o[n] = v;
}

// ---------------- launch ----------------------------------------------------
extern "C" void kernel_launch(void* const* d_in, const int* in_sizes, int n_in,
                              void* d_out, int out_size) {
    const float* X  = (const float*)d_in[0];
    const float* Wg = (const float*)d_in[1];
    const float* bg = (const float*)d_in[2];
    const float* W1 = (const float*)d_in[3];
    const float* b1 = (const float*)d_in[4];
    const float* W2 = (const float*)d_in[5];
    const float* b2 = (const float*)d_in[6];
    float* out = (float*)d_out;

    cudaFuncSetAttribute((const void*)gemm_mma<HDIM, MDIM, true>,
                         cudaFuncAttributeMaxDynamicSharedMemorySize, SMEM_BYTES);
    cudaFuncSetAttribute((const void*)gemm_mma<MDIM, HDIM, false>,
                         cudaFuncAttributeMaxDynamicSharedMemorySize, SMEM_BYTES);

    zero_counts_kernel<<<1, 32>>>();
    gate_kernel<<<T_TOK, 128>>>(X, Wg, bg);
    scan_kernel<<<1, 32>>>();
    scatter_kernel<<<(NASSIGN + 255) / 256, 256>>>();

    gather_convert_x<<<NASSIGN, 128>>>(X);
    {
        __half *w1t, *w2t;
        cudaGetSymbolAddress((void**)&w1t, g_W1t);
        cudaGetSymbolAddress((void**)&w2t, g_W2t);
        trans_convert<HDIM, MDIM><<<dim3(MDIM / 32, HDIM / 32, NEXP), 256>>>(W1, w1t);
        trans_convert<MDIM, HDIM><<<dim3(HDIM / 32, MDIM / 32, NEXP), 256>>>(W2, w2t);
    }

    // GEMM1: gathered X [*,1024] x W1t[e][2048,1024] -> H (relu, f16)
    gemm_mma<HDIM, MDIM, true ><<<dim3(MDIM / BN, MAX_TILES), 256, SMEM_BYTES>>>(b1);
    // GEMM2: H [*,2048] x W2t[e][1024,2048] -> Y (fp32)
    gemm_mma<MDIM, HDIM, false><<<dim3(HDIM / BN, MAX_TILES), 256, SMEM_BYTES>>>(b2);

    combine_kernel<<<T_TOK, 256>>>(out);
}